// round 1
// baseline (speedup 1.0000x reference)
#include <cuda_runtime.h>
#include <math.h>

#define NB 4
#define NS 512
#define NDIM 512
#define NH 8
#define NDH 64
#define NM (NB*NS)     // 2048
#define PAD 68         // smem row stride (floats): 16B-aligned rows, low bank conflict

// ---------------- device scratch (no allocations allowed) ----------------
__device__ float g_q[NB*NH*NS*NDH];     // [b][h][s][d]
__device__ float g_k[NB*NH*NS*NDH];
__device__ float g_v[NB*NH*NS*NDH];
__device__ float g_u[NB*NS*NH];         // [b][s][h]
__device__ float g_w[NB*NH*NS];         // [b][h][k] : q-independent positional attention row
__device__ float g_attn[NB*NH*NS*NS];   // [b][h][q][k] scores -> combined probs (in place)
__device__ float g_y[NM*NDIM];          // pre-output-projection activations

// ---------------- shared 64x64 fp32 GEMM core (NN: B row-major K x N) ----
__device__ __forceinline__ void gemm64(const float* __restrict__ A, int lda,
                                       const float* __restrict__ B, int ldb,
                                       int K, float (&acc)[4][4],
                                       float (*As)[PAD], float (*Bs)[64]) {
    int tid = threadIdx.x;
    int tx = tid & 15, ty = tid >> 4;
    for (int k0 = 0; k0 < K; k0 += 16) {
        #pragma unroll
        for (int l = 0; l < 4; l++) {
            int idx = tid + l * 256;
            int i = idx >> 4, j = idx & 15;
            As[j][i] = A[i * lda + k0 + j];
        }
        #pragma unroll
        for (int l = 0; l < 4; l++) {
            int idx = tid + l * 256;
            int kk = idx >> 6, n = idx & 63;
            Bs[kk][n] = B[(k0 + kk) * ldb + n];
        }
        __syncthreads();
        #pragma unroll
        for (int kk = 0; kk < 16; kk++) {
            float4 bv = *(const float4*)&Bs[kk][tx * 4];
            float a0 = As[kk][ty * 4 + 0];
            float a1 = As[kk][ty * 4 + 1];
            float a2 = As[kk][ty * 4 + 2];
            float a3 = As[kk][ty * 4 + 3];
            acc[0][0] += a0 * bv.x; acc[0][1] += a0 * bv.y; acc[0][2] += a0 * bv.z; acc[0][3] += a0 * bv.w;
            acc[1][0] += a1 * bv.x; acc[1][1] += a1 * bv.y; acc[1][2] += a1 * bv.z; acc[1][3] += a1 * bv.w;
            acc[2][0] += a2 * bv.x; acc[2][1] += a2 * bv.y; acc[2][2] += a2 * bv.z; acc[2][3] += a2 * bv.w;
            acc[3][0] += a3 * bv.x; acc[3][1] += a3 * bv.y; acc[3][2] += a3 * bv.z; acc[3][3] += a3 * bv.w;
        }
        __syncthreads();
    }
}

// NT variant: both operands row-major with K contiguous (Q[64,K] x Kt[64,K]^T)
__device__ __forceinline__ void gemm64_nt(const float* __restrict__ A, int lda,
                                          const float* __restrict__ Bt, int ldb,
                                          int K, float (&acc)[4][4],
                                          float (*As)[PAD], float (*Bs)[PAD]) {
    int tid = threadIdx.x;
    int tx = tid & 15, ty = tid >> 4;
    for (int k0 = 0; k0 < K; k0 += 16) {
        #pragma unroll
        for (int l = 0; l < 4; l++) {
            int idx = tid + l * 256;
            int i = idx >> 4, j = idx & 15;
            As[j][i] = A[i * lda + k0 + j];
            Bs[j][i] = Bt[i * ldb + k0 + j];
        }
        __syncthreads();
        #pragma unroll
        for (int kk = 0; kk < 16; kk++) {
            float4 bv = *(const float4*)&Bs[kk][tx * 4];
            float a0 = As[kk][ty * 4 + 0];
            float a1 = As[kk][ty * 4 + 1];
            float a2 = As[kk][ty * 4 + 2];
            float a3 = As[kk][ty * 4 + 3];
            acc[0][0] += a0 * bv.x; acc[0][1] += a0 * bv.y; acc[0][2] += a0 * bv.z; acc[0][3] += a0 * bv.w;
            acc[1][0] += a1 * bv.x; acc[1][1] += a1 * bv.y; acc[1][2] += a1 * bv.z; acc[1][3] += a1 * bv.w;
            acc[2][0] += a2 * bv.x; acc[2][1] += a2 * bv.y; acc[2][2] += a2 * bv.z; acc[2][3] += a2 * bv.w;
            acc[3][0] += a3 * bv.x; acc[3][1] += a3 * bv.y; acc[3][2] += a3 * bv.z; acc[3][3] += a3 * bv.w;
        }
        __syncthreads();
    }
}

// ---------------- tiny positional MLP: u[b,s,h] = (relu(pos@Wp1+bp1)@Wp2+bp2)@Wh
__global__ void u_kernel(const float* __restrict__ pos,
                         const float* __restrict__ Wp1, const float* __restrict__ bp1,
                         const float* __restrict__ Wp2, const float* __restrict__ bp2,
                         const float* __restrict__ Wh) {
    int idx = blockIdx.x * blockDim.x + threadIdx.x;
    if (idx >= NM) return;
    const float* pp = pos + idx * 3;
    float p0 = pp[0], p1 = pp[1], p2 = pp[2];
    float h1[3];
    #pragma unroll
    for (int j = 0; j < 3; j++)
        h1[j] = fmaxf(0.0f, p0 * Wp1[j] + p1 * Wp1[3 + j] + p2 * Wp1[6 + j] + bp1[j]);
    float u[NH];
    #pragma unroll
    for (int hh = 0; hh < NH; hh++) u[hh] = 0.0f;
    for (int j = 0; j < 64; j++) {
        float pv = h1[0] * Wp2[j] + h1[1] * Wp2[64 + j] + h1[2] * Wp2[128 + j] + bp2[j];
        #pragma unroll
        for (int hh = 0; hh < NH; hh++) u[hh] += pv * Wh[j * NH + hh];
    }
    #pragma unroll
    for (int hh = 0; hh < NH; hh++) g_u[idx * NH + hh] = u[hh];
}

// w[b,h,k] = softmax_k(-u[b,k,h])  (pos-attn row: q-independent after cancellation)
__global__ void pos_w_kernel() {
    __shared__ float red[512];
    int bh = blockIdx.x;
    int b = bh >> 3, h = bh & 7;
    int k = threadIdx.x;
    float t = -g_u[(b * NS + k) * NH + h];
    red[k] = t; __syncthreads();
    for (int s = 256; s > 0; s >>= 1) { if (k < s) red[k] = fmaxf(red[k], red[k + s]); __syncthreads(); }
    float m = red[0]; __syncthreads();
    float e = expf(t - m);
    red[k] = e; __syncthreads();
    for (int s = 256; s > 0; s >>= 1) { if (k < s) red[k] += red[k + s]; __syncthreads(); }
    g_w[bh * NS + k] = e / red[0];
}

// ---------------- QKV projection: q/k/v[b,h,s,d] = (x @ W)[b*512+s, h*64+d]
__global__ void qkv_gemm(const float* __restrict__ X, const float* __restrict__ Wq,
                         const float* __restrict__ Wk, const float* __restrict__ Wv) {
    __shared__ float As[16][PAD];
    __shared__ float Bs[16][64];
    const float* W = (blockIdx.z == 0) ? Wq : ((blockIdx.z == 1) ? Wk : Wv);
    float* out = (blockIdx.z == 0) ? g_q : ((blockIdx.z == 1) ? g_k : g_v);
    int m0 = blockIdx.y * 64, n0 = blockIdx.x * 64;
    float acc[4][4] = {};
    gemm64(X + m0 * NDIM, NDIM, W + n0, NDIM, NDIM, acc, As, Bs);
    int tx = threadIdx.x & 15, ty = threadIdx.x >> 4;
    #pragma unroll
    for (int i = 0; i < 4; i++)
        #pragma unroll
        for (int j = 0; j < 4; j++) {
            int m = m0 + ty * 4 + i, n = n0 + tx * 4 + j;
            int b = m >> 9, s = m & 511, h = n >> 6, d = n & 63;
            out[((b * NH + h) * NS + s) * NDH + d] = acc[i][j];
        }
}

// ---------------- scores[b,h,q,k] = q . k / 8
__global__ void scores_kernel() {
    __shared__ float Qs[16][PAD];
    __shared__ float Ks[16][PAD];
    int bh = blockIdx.z;
    const float* Q = g_q + bh * NS * NDH + blockIdx.y * 64 * NDH;
    const float* K = g_k + bh * NS * NDH + blockIdx.x * 64 * NDH;
    float acc[4][4] = {};
    gemm64_nt(Q, NDH, K, NDH, NDH, acc, Qs, Ks);
    float* out = g_attn + bh * NS * NS;
    int q0 = blockIdx.y * 64, k0 = blockIdx.x * 64;
    int tx = threadIdx.x & 15, ty = threadIdx.x >> 4;
    #pragma unroll
    for (int i = 0; i < 4; i++)
        #pragma unroll
        for (int j = 0; j < 4; j++)
            out[(q0 + ty * 4 + i) * NS + k0 + tx * 4 + j] = acc[i][j] * 0.125f;
}

// ---------------- row softmax + sigmoid-gate blend with positional row w
__global__ void softmax_combine(const float* __restrict__ gate) {
    __shared__ float red[256];
    int row = blockIdx.x;          // = bh*512 + q
    int bh = row >> 9;
    int h = bh & 7;
    float* a = g_attn + row * NS;
    const float* w = g_w + bh * NS;
    int t = threadIdx.x;
    float v0 = a[t], v1 = a[t + 256];
    red[t] = fmaxf(v0, v1); __syncthreads();
    for (int s = 128; s > 0; s >>= 1) { if (t < s) red[t] = fmaxf(red[t], red[t + s]); __syncthreads(); }
    float m = red[0]; __syncthreads();
    float e0 = expf(v0 - m), e1 = expf(v1 - m);
    red[t] = e0 + e1; __syncthreads();
    for (int s = 128; s > 0; s >>= 1) { if (t < s) red[t] += red[t + s]; __syncthreads(); }
    float inv = 1.0f / red[0];
    float g = 1.0f / (1.0f + expf(-gate[h]));
    float og = 1.0f - g;
    a[t]       = og * e0 * inv + g * w[t];
    a[t + 256] = og * e1 * inv + g * w[t + 256];
}

// ---------------- PV: y[b, q, h*64+d] = sum_k combined[b,h,q,k] * v[b,h,k,d]
__global__ void pv_kernel() {
    __shared__ float As[16][PAD];
    __shared__ float Bs[16][64];
    int bh = blockIdx.z;
    int b = bh >> 3, h = bh & 7;
    const float* A = g_attn + bh * NS * NS + blockIdx.y * 64 * NS;
    const float* Bv = g_v + bh * NS * NDH;
    float acc[4][4] = {};
    gemm64(A, NS, Bv, NDH, NS, acc, As, Bs);
    int q0 = blockIdx.y * 64;
    int tx = threadIdx.x & 15, ty = threadIdx.x >> 4;
    #pragma unroll
    for (int i = 0; i < 4; i++)
        #pragma unroll
        for (int j = 0; j < 4; j++) {
            int q = q0 + ty * 4 + i, d = tx * 4 + j;
            g_y[(b * NS + q) * NDIM + h * NDH + d] = acc[i][j];
        }
}

// ---------------- out = y @ Wo + bo
__global__ void out_gemm(const float* __restrict__ Wo, const float* __restrict__ bo,
                         float* __restrict__ out) {
    __shared__ float As[16][PAD];
    __shared__ float Bs[16][64];
    int m0 = blockIdx.y * 64, n0 = blockIdx.x * 64;
    float acc[4][4] = {};
    gemm64(g_y + m0 * NDIM, NDIM, Wo + n0, NDIM, NDIM, acc, As, Bs);
    int tx = threadIdx.x & 15, ty = threadIdx.x >> 4;
    #pragma unroll
    for (int i = 0; i < 4; i++)
        #pragma unroll
        for (int j = 0; j < 4; j++) {
            int m = m0 + ty * 4 + i, n = n0 + tx * 4 + j;
            out[m * NDIM + n] = acc[i][j] + bo[n];
        }
}

extern "C" void kernel_launch(void* const* d_in, const int* in_sizes, int n_in,
                              void* d_out, int out_size) {
    const float* x    = (const float*)d_in[0];
    const float* pos  = (const float*)d_in[1];
    const float* Wq   = (const float*)d_in[2];
    const float* Wk   = (const float*)d_in[3];
    const float* Wv   = (const float*)d_in[4];
    const float* Wo   = (const float*)d_in[5];
    const float* bo   = (const float*)d_in[6];
    const float* Wp1  = (const float*)d_in[7];
    const float* bp1  = (const float*)d_in[8];
    const float* Wp2  = (const float*)d_in[9];
    const float* bp2  = (const float*)d_in[10];
    const float* Wh   = (const float*)d_in[11];
    // d_in[12] = bh : cancels inside softmax (constant along k axis) — unused
    const float* gate = (const float*)d_in[13];
    float* out = (float*)d_out;

    u_kernel<<<8, 256>>>(pos, Wp1, bp1, Wp2, bp2, Wh);
    pos_w_kernel<<<32, 512>>>();
    qkv_gemm<<<dim3(8, 32, 3), 256>>>(x, Wq, Wk, Wv);
    scores_kernel<<<dim3(8, 8, 32), 256>>>();
    softmax_combine<<<16384, 256>>>(gate);
    pv_kernel<<<dim3(1, 8, 32), 256>>>();
    out_gemm<<<dim3(8, 32), 256>>>(Wo, bo, out);
}

// round 3
// speedup vs baseline: 1.0608x; 1.0608x over previous
#include <cuda_runtime.h>
#include <math.h>

#define NB 4
#define NS 512
#define NDIM 512
#define NH 8
#define NDH 64
#define NM (NB*NS)     // 2048

// ---------------- device scratch (no allocations allowed) ----------------
__device__ float g_q[NB*NH*NS*NDH];     // [b][h][s][d]
__device__ float g_k[NB*NH*NS*NDH];
__device__ float g_v[NB*NH*NS*NDH];
__device__ float g_u[NB*NS*NH];         // [b][s][h]
__device__ float g_w[NB*NH*NS];         // [b][h][k] : q-independent positional attn row
__device__ float g_y[NM*NDIM];          // pre-output-projection activations

// =====================================================================
// 128x128 block-tile GEMM core, 8x8 per thread, 256 threads.
// A row-major [M,K] lda; B row-major [K,N] ldb. K must be multiple of 16.
// =====================================================================
__device__ __forceinline__ void gemm128_core(const float* __restrict__ A, int lda,
                                             const float* __restrict__ B, int ldb,
                                             int K, float (&acc)[8][8],
                                             float (*As)[132], float (*Bs)[128]) {
    int tid = threadIdx.x;
    int tx = tid & 15, ty = tid >> 4;
    int arow = tid >> 1, acol = (tid & 1) * 8;   // 128 rows x 16 k, 8 floats/thread
    int brow = tid >> 4, bcol = (tid & 15) * 8;  // 16 k x 128 n

    for (int k0 = 0; k0 < K; k0 += 16) {
        float4 av0 = *(const float4*)&A[arow * lda + k0 + acol];
        float4 av1 = *(const float4*)&A[arow * lda + k0 + acol + 4];
        As[acol + 0][arow] = av0.x;
        As[acol + 1][arow] = av0.y;
        As[acol + 2][arow] = av0.z;
        As[acol + 3][arow] = av0.w;
        As[acol + 4][arow] = av1.x;
        As[acol + 5][arow] = av1.y;
        As[acol + 6][arow] = av1.z;
        As[acol + 7][arow] = av1.w;
        *(float4*)&Bs[brow][bcol]     = *(const float4*)&B[(k0 + brow) * ldb + bcol];
        *(float4*)&Bs[brow][bcol + 4] = *(const float4*)&B[(k0 + brow) * ldb + bcol + 4];
        __syncthreads();
        #pragma unroll
        for (int kk = 0; kk < 16; kk++) {
            float4 a0 = *(float4*)&As[kk][ty * 4];
            float4 a1 = *(float4*)&As[kk][64 + ty * 4];
            float4 b0 = *(float4*)&Bs[kk][tx * 4];
            float4 b1 = *(float4*)&Bs[kk][64 + tx * 4];
            float a[8] = {a0.x, a0.y, a0.z, a0.w, a1.x, a1.y, a1.z, a1.w};
            float b[8] = {b0.x, b0.y, b0.z, b0.w, b1.x, b1.y, b1.z, b1.w};
            #pragma unroll
            for (int i = 0; i < 8; i++)
                #pragma unroll
                for (int j = 0; j < 8; j++)
                    acc[i][j] += a[i] * b[j];
        }
        __syncthreads();
    }
}

// ---------------- QKV projection with scatter to [b,h,s,d] ----------------
__global__ void qkv_gemm(const float* __restrict__ X, const float* __restrict__ Wq,
                         const float* __restrict__ Wk, const float* __restrict__ Wv) {
    __shared__ float As[16][132];
    __shared__ float Bs[16][128];
    const float* W = (blockIdx.z == 0) ? Wq : ((blockIdx.z == 1) ? Wk : Wv);
    float* out = (blockIdx.z == 0) ? g_q : ((blockIdx.z == 1) ? g_k : g_v);
    int m0 = blockIdx.y * 128, n0 = blockIdx.x * 128;
    float acc[8][8] = {};
    gemm128_core(X + m0 * NDIM, NDIM, W + n0, NDIM, NDIM, acc, As, Bs);
    int tx = threadIdx.x & 15, ty = threadIdx.x >> 4;
    #pragma unroll
    for (int i = 0; i < 8; i++) {
        int m = m0 + ((i < 4) ? ty * 4 + i : 64 + ty * 4 + (i - 4));
        int b = m >> 9, s = m & 511;
        #pragma unroll
        for (int jh = 0; jh < 2; jh++) {
            int n = n0 + (jh ? 64 + tx * 4 : tx * 4);
            int h = n >> 6, d = n & 63;
            float4 v = make_float4(acc[i][jh * 4 + 0], acc[i][jh * 4 + 1],
                                   acc[i][jh * 4 + 2], acc[i][jh * 4 + 3]);
            *(float4*)&out[((b * NH + h) * NS + s) * NDH + d] = v;
        }
    }
}

// ---------------- out = y @ Wo + bo ----------------
__global__ void out_gemm(const float* __restrict__ Wo, const float* __restrict__ bo,
                         float* __restrict__ out) {
    __shared__ float As[16][132];
    __shared__ float Bs[16][128];
    int m0 = blockIdx.y * 128, n0 = blockIdx.x * 128;
    float acc[8][8] = {};
    gemm128_core(g_y + m0 * NDIM, NDIM, Wo + n0, NDIM, NDIM, acc, As, Bs);
    int tx = threadIdx.x & 15, ty = threadIdx.x >> 4;
    #pragma unroll
    for (int i = 0; i < 8; i++) {
        int m = m0 + ((i < 4) ? ty * 4 + i : 64 + ty * 4 + (i - 4));
        #pragma unroll
        for (int jh = 0; jh < 2; jh++) {
            int n = n0 + (jh ? 64 + tx * 4 : tx * 4);
            float4 v = make_float4(acc[i][jh * 4 + 0] + bo[n + 0], acc[i][jh * 4 + 1] + bo[n + 1],
                                   acc[i][jh * 4 + 2] + bo[n + 2], acc[i][jh * 4 + 3] + bo[n + 3]);
            *(float4*)&out[m * NDIM + n] = v;
        }
    }
}

// ---------------- tiny positional MLP: u[b,s,h] ----------------
__global__ void u_kernel(const float* __restrict__ pos,
                         const float* __restrict__ Wp1, const float* __restrict__ bp1,
                         const float* __restrict__ Wp2, const float* __restrict__ bp2,
                         const float* __restrict__ Wh) {
    int idx = blockIdx.x * blockDim.x + threadIdx.x;
    if (idx >= NM) return;
    const float* pp = pos + idx * 3;
    float p0 = pp[0], p1 = pp[1], p2 = pp[2];
    float h1[3];
    #pragma unroll
    for (int j = 0; j < 3; j++)
        h1[j] = fmaxf(0.0f, p0 * Wp1[j] + p1 * Wp1[3 + j] + p2 * Wp1[6 + j] + bp1[j]);
    float u[NH];
    #pragma unroll
    for (int hh = 0; hh < NH; hh++) u[hh] = 0.0f;
    for (int j = 0; j < 64; j++) {
        float pv = h1[0] * Wp2[j] + h1[1] * Wp2[64 + j] + h1[2] * Wp2[128 + j] + bp2[j];
        #pragma unroll
        for (int hh = 0; hh < NH; hh++) u[hh] += pv * Wh[j * NH + hh];
    }
    #pragma unroll
    for (int hh = 0; hh < NH; hh++) g_u[idx * NH + hh] = u[hh];
}

// w[b,h,k] = softmax_k(-u[b,k,h])
__global__ void pos_w_kernel() {
    __shared__ float red[512];
    int bh = blockIdx.x;
    int b = bh >> 3, h = bh & 7;
    int k = threadIdx.x;
    float t = -g_u[(b * NS + k) * NH + h];
    red[k] = t; __syncthreads();
    for (int s = 256; s > 0; s >>= 1) { if (k < s) red[k] = fmaxf(red[k], red[k + s]); __syncthreads(); }
    float m = red[0]; __syncthreads();
    float e = expf(t - m);
    red[k] = e; __syncthreads();
    for (int s = 256; s > 0; s >>= 1) { if (k < s) red[k] += red[k + s]; __syncthreads(); }
    g_w[bh * NS + k] = e / red[0];
}

// =====================================================================
// Fused attention: scores + softmax + gate-combine + PV, per (bh, q-tile 64).
// Score tile S[64,512] lives in smem; K/V streamed in chunks.
// =====================================================================
#define S_LD 516          // S row stride (floats), 16B aligned
#define SM_S    (64 * S_LD)            // 33024
#define SM_QS   (64 * 68)              // 4352
#define SM_KS   (64 * 132)             // 8448
#define SM_W    512
#define SMEM_FLOATS (SM_S + SM_QS + SM_KS + SM_W)   // 46336
#define SMEM_BYTES  (SMEM_FLOATS * 4)                // 185344

__global__ void attn_fused(const float* __restrict__ gate) {
    extern __shared__ float sm[];
    float* S = sm;                                     // [64][516]
    float (*Qs)[68]  = (float(*)[68]) (sm + SM_S);     // [d][q]
    float (*Ks)[132] = (float(*)[132])(sm + SM_S + SM_QS);  // [d][kr] (128 kr)
    float (*Vs)[68]  = (float(*)[68]) (sm + SM_S + SM_QS);  // reuse: [kk][d]
    float* wrow = sm + SM_S + SM_QS + SM_KS;

    int tid = threadIdx.x;
    int bh = blockIdx.y;
    int q0 = blockIdx.x * 64;
    int h = bh & 7;
    int b = bh >> 3;
    const float* Qg = g_q + (size_t)bh * NS * NDH;
    const float* Kg = g_k + (size_t)bh * NS * NDH;
    const float* Vg = g_v + (size_t)bh * NS * NDH;

    float gv = 1.0f / (1.0f + __expf(-gate[h]));
    float og = 1.0f - gv;

    // load Q tile transposed: Qs[d][q]
    {
        int q = tid >> 2;
        int d0 = (tid & 3) * 16;
        #pragma unroll
        for (int c = 0; c < 4; c++) {
            float4 v = *(const float4*)&Qg[(q0 + q) * NDH + d0 + c * 4];
            Qs[d0 + c * 4 + 0][q] = v.x;
            Qs[d0 + c * 4 + 1][q] = v.y;
            Qs[d0 + c * 4 + 2][q] = v.z;
            Qs[d0 + c * 4 + 3][q] = v.w;
        }
        wrow[tid]       = g_w[bh * NS + tid];
        wrow[tid + 256] = g_w[bh * NS + tid + 256];
    }
    __syncthreads();

    int tx = tid & 15, ty = tid >> 4;

    // ---- Phase 1: S = Q K^T / 8, in 4 chunks of 128 k-rows ----
    for (int kc = 0; kc < 4; kc++) {
        {   // load 128 K rows transposed: Ks[d][kr]
            int kr = tid >> 1;
            int dbase = (tid & 1) * 32;
            #pragma unroll
            for (int c = 0; c < 8; c++) {
                float4 v = *(const float4*)&Kg[(kc * 128 + kr) * NDH + dbase + c * 4];
                Ks[dbase + c * 4 + 0][kr] = v.x;
                Ks[dbase + c * 4 + 1][kr] = v.y;
                Ks[dbase + c * 4 + 2][kr] = v.z;
                Ks[dbase + c * 4 + 3][kr] = v.w;
            }
        }
        __syncthreads();
        float acc[4][8] = {};
        #pragma unroll
        for (int d = 0; d < 64; d++) {
            float4 a  = *(float4*)&Qs[d][ty * 4];
            float4 b0 = *(float4*)&Ks[d][tx * 4];
            float4 b1 = *(float4*)&Ks[d][64 + tx * 4];
            float av[4] = {a.x, a.y, a.z, a.w};
            float bv[8] = {b0.x, b0.y, b0.z, b0.w, b1.x, b1.y, b1.z, b1.w};
            #pragma unroll
            for (int i = 0; i < 4; i++)
                #pragma unroll
                for (int j = 0; j < 8; j++)
                    acc[i][j] += av[i] * bv[j];
        }
        #pragma unroll
        for (int i = 0; i < 4; i++) {
            int r = ty * 4 + i;
            float4 v0 = make_float4(acc[i][0] * 0.125f, acc[i][1] * 0.125f,
                                    acc[i][2] * 0.125f, acc[i][3] * 0.125f);
            float4 v1 = make_float4(acc[i][4] * 0.125f, acc[i][5] * 0.125f,
                                    acc[i][6] * 0.125f, acc[i][7] * 0.125f);
            *(float4*)&S[r * S_LD + kc * 128 + tx * 4]      = v0;
            *(float4*)&S[r * S_LD + kc * 128 + 64 + tx * 4] = v1;
        }
        __syncthreads();
    }

    // ---- Phase 2: row softmax + gate blend (8 warps x 8 rows each) ----
    {
        int lane = tid & 31;
        int w = tid >> 5;
        for (int rr = 0; rr < 8; rr++) {
            float* row = S + (w * 8 + rr) * S_LD;
            float m = -1e30f;
            #pragma unroll
            for (int i = 0; i < 16; i++) m = fmaxf(m, row[lane + 32 * i]);
            #pragma unroll
            for (int off = 16; off > 0; off >>= 1)
                m = fmaxf(m, __shfl_xor_sync(0xFFFFFFFF, m, off));
            float s = 0.0f;
            #pragma unroll
            for (int i = 0; i < 16; i++) {
                float e = __expf(row[lane + 32 * i] - m);
                row[lane + 32 * i] = e;
                s += e;
            }
            #pragma unroll
            for (int off = 16; off > 0; off >>= 1)
                s += __shfl_xor_sync(0xFFFFFFFF, s, off);
            float inv = og / s;
            #pragma unroll
            for (int i = 0; i < 16; i++) {
                int idx = lane + 32 * i;
                row[idx] = row[idx] * inv + gv * wrow[idx];
            }
        }
    }
    __syncthreads();

    // ---- Phase 3: O[64,64] = S[64,512] @ V[512,64], 8 chunks of 64 ----
    float o[4][4] = {};
    for (int vc = 0; vc < 8; vc++) {
        {   // load V chunk: Vs[kk][d]
            int kk = tid >> 2;
            int d0 = (tid & 3) * 16;
            #pragma unroll
            for (int c = 0; c < 4; c++)
                *(float4*)&Vs[kk][d0 + c * 4] =
                    *(const float4*)&Vg[(vc * 64 + kk) * NDH + d0 + c * 4];
        }
        __syncthreads();
        #pragma unroll
        for (int k4 = 0; k4 < 64; k4 += 4) {
            float4 ar[4];
            #pragma unroll
            for (int i = 0; i < 4; i++)
                ar[i] = *(float4*)&S[(ty * 4 + i) * S_LD + vc * 64 + k4];
            float a[4][4] = {{ar[0].x, ar[0].y, ar[0].z, ar[0].w},
                             {ar[1].x, ar[1].y, ar[1].z, ar[1].w},
                             {ar[2].x, ar[2].y, ar[2].z, ar[2].w},
                             {ar[3].x, ar[3].y, ar[3].z, ar[3].w}};
            #pragma unroll
            for (int kk = 0; kk < 4; kk++) {
                float4 bv = *(float4*)&Vs[k4 + kk][tx * 4];
                float bb[4] = {bv.x, bv.y, bv.z, bv.w};
                #pragma unroll
                for (int i = 0; i < 4; i++)
                    #pragma unroll
                    for (int j = 0; j < 4; j++)
                        o[i][j] += a[i][kk] * bb[j];
            }
        }
        __syncthreads();
    }
    #pragma unroll
    for (int i = 0; i < 4; i++) {
        int q = q0 + ty * 4 + i;
        float4 v = make_float4(o[i][0], o[i][1], o[i][2], o[i][3]);
        *(float4*)&g_y[((size_t)b * NS + q) * NDIM + h * NDH + tx * 4] = v;
    }
}

extern "C" void kernel_launch(void* const* d_in, const int* in_sizes, int n_in,
                              void* d_out, int out_size) {
    const float* x    = (const float*)d_in[0];
    const float* pos  = (const float*)d_in[1];
    const float* Wq   = (const float*)d_in[2];
    const float* Wk   = (const float*)d_in[3];
    const float* Wv   = (const float*)d_in[4];
    const float* Wo   = (const float*)d_in[5];
    const float* bo   = (const float*)d_in[6];
    const float* Wp1  = (const float*)d_in[7];
    const float* bp1  = (const float*)d_in[8];
    const float* Wp2  = (const float*)d_in[9];
    const float* bp2  = (const float*)d_in[10];
    const float* Wh   = (const float*)d_in[11];
    // d_in[12] = bh : cancels inside softmax (constant along k axis) — unused
    const float* gate = (const float*)d_in[13];
    float* out = (float*)d_out;

    static bool attr_set = false;
    if (!attr_set) {
        cudaFuncSetAttribute(attn_fused, cudaFuncAttributeMaxDynamicSharedMemorySize, SMEM_BYTES);
        attr_set = true;
    }

    u_kernel<<<8, 256>>>(pos, Wp1, bp1, Wp2, bp2, Wh);
    pos_w_kernel<<<32, 512>>>();
    qkv_gemm<<<dim3(4, 16, 3), 256>>>(x, Wq, Wk, Wv);
    attn_fused<<<dim3(8, 32), 256, SMEM_BYTES>>>(gate);
    out_gemm<<<dim3(4, 16), 256>>>(Wo, bo, out);
}